// round 14
// baseline (speedup 1.0000x reference)
#include <cuda_runtime.h>
#include <cuda_fp16.h>
#include <math.h>
#include <stdint.h>

#define NMAX 100000
#define EMAX 1600000
#define HDIM 128
#define NPBLK 296   // persistent grid: 2 CTAs/SM x 148 SMs (<= resident on 152-SM GB300 too)

// ---------------- scratch (device globals; referenced by name only) --------
__device__ __align__(16) __half g_m [NMAX * HDIM];   // aggregated max (fp16)
__device__ __align__(16) __half g_fh[NMAX * HDIM];   // current layer state (fp16)
__device__ int   g_deg[NMAX];
__device__ int   g_off[NMAX + 1];
__device__ int   g_cur[NMAX];
__device__ int   g_csr[EMAX];
__device__ int   g_bsum[128];
__device__ int   g_flag[128];
__device__ int   g_barCnt;
// fp16 weights in mma-ready layout: [3][8 kc][128 col][16 half2]
__device__ __align__(16) uint32_t g_Wh[3 * 8 * 128 * 16];

#define MMA_F16(d, a, b0v, b1v) \
    asm volatile( \
        "mma.sync.aligned.m16n8k16.row.col.f32.f16.f16.f32 " \
        "{%0,%1,%2,%3}, {%4,%5,%6,%7}, {%8,%9}, {%0,%1,%2,%3};" \
        : "+f"((d)[0]), "+f"((d)[1]), "+f"((d)[2]), "+f"((d)[3]) \
        : "r"((a)[0]), "r"((a)[1]), "r"((a)[2]), "r"((a)[3]), \
          "r"(b0v), "r"(b1v))

// ---------------- fused setup: zeroing, x->fp16 mirror, weight prep --------
__global__ void k_setup(const float* __restrict__ x,
                        const float* __restrict__ W1l, const float* __restrict__ W1r,
                        const float* __restrict__ W2l, const float* __restrict__ W2r,
                        const float* __restrict__ W3l, const float* __restrict__ W3r,
                        int n, int total4) {
    int i = blockIdx.x * blockDim.x + threadIdx.x;
    if (i == 0) g_barCnt = 0;
    if (i < total4) {
        float4 f = ((const float4*)x)[i];
        __half2 h0 = __floats2half2_rn(f.x, f.y);
        __half2 h1 = __floats2half2_rn(f.z, f.w);
        uint2 u;
        u.x = *(uint32_t*)&h0;
        u.y = *(uint32_t*)&h1;
        ((uint2*)g_fh)[i] = u;
    }
    if (i < n) g_deg[i] = 0;
    if (i < 128) g_flag[i] = 0;
    if (i < 3 * 8 * 128 * 16) {
        int widx = i >> 14;
        int rem  = i & 16383;
        int kc   = rem >> 11;
        int rem2 = rem & 2047;
        int col  = rem2 >> 4;
        int hp   = rem2 & 15;
        int k    = kc * 32 + hp * 2;
        const float* Wl = (widx == 0) ? W1l : (widx == 1) ? W2l : W3l;
        const float* Wr = (widx == 0) ? W1r : (widx == 1) ? W2r : W3r;
        float v0 = (k < HDIM)     ? Wl[col * HDIM + k]     : Wr[col * HDIM + k - HDIM];
        float v1 = (k + 1 < HDIM) ? Wl[col * HDIM + k + 1] : Wr[col * HDIM + k + 1 - HDIM];
        __half2 h = __floats2half2_rn(v0, v1);
        g_Wh[i] = *(uint32_t*)&h;
    }
}

// ---------------- CSR build ------------------------------------------------
__global__ void k_hist(const int* __restrict__ ei, int E, int n) {
    int t  = blockIdx.x * blockDim.x + threadIdx.x;
    int e4 = t * 4;
    if (e4 + 3 < E) {
        int4 d = *(const int4*)(ei + E + e4);
        if ((unsigned)d.x < (unsigned)n) atomicAdd(&g_deg[d.x], 1);
        if ((unsigned)d.y < (unsigned)n) atomicAdd(&g_deg[d.y], 1);
        if ((unsigned)d.z < (unsigned)n) atomicAdd(&g_deg[d.z], 1);
        if ((unsigned)d.w < (unsigned)n) atomicAdd(&g_deg[d.w], 1);
    } else {
        for (int e = e4; e < E; e++) {
            int d = ei[E + e];
            if ((unsigned)d < (unsigned)n) atomicAdd(&g_deg[d], 1);
        }
    }
}

// single-kernel exclusive scan (all blocks resident; parallel aggregate read)
__global__ void k_scan_all(int n, int E) {
    __shared__ int s[1024];
    __shared__ int s2[1024];
    int tid = threadIdx.x;
    int bid = blockIdx.x;
    int gid = bid * 1024 + tid;
    int v = (gid < n) ? g_deg[gid] : 0;
    s[tid] = v;
    __syncthreads();
    for (int d = 1; d < 1024; d <<= 1) {
        int t = (tid >= d) ? s[tid - d] : 0;
        __syncthreads();
        s[tid] += t;
        __syncthreads();
    }
    if (tid == 0) {
        g_bsum[bid] = s[1023];
        __threadfence();
        atomicExch(&g_flag[bid], 1);
    }
    int pv = 0;
    if (tid < bid) {
        while (atomicAdd(&g_flag[tid], 0) == 0) {}
        pv = atomicAdd(&g_bsum[tid], 0);
    }
    s2[tid] = pv;
    __syncthreads();
    for (int d = 512; d > 0; d >>= 1) {
        if (tid < d) s2[tid] += s2[tid + d];
        __syncthreads();
    }
    int prefix = s2[0];
    if (gid < n) {
        int o = s[tid] - v + prefix;
        g_off[gid] = o;
        g_cur[gid] = o;
    } else if (gid == n) {
        g_off[n] = E;
    }
}

// scalar fill (R11-measured faster than int4 variant)
__global__ void k_fill(const int* __restrict__ ei, int E, int n) {
    int e = blockIdx.x * blockDim.x + threadIdx.x;
    if (e < E) {
        int s = ei[e];
        int d = ei[E + e];
        if ((unsigned)s < (unsigned)n && (unsigned)d < (unsigned)n) {
            int pos = atomicAdd(&g_cur[d], 1);
            if ((unsigned)pos < (unsigned)E) g_csr[pos] = s;
        }
    }
}

// ---------------- grid barrier (persistent kernel, monotonic counter) ------
__device__ __forceinline__ void grid_bar(int target) {
    __syncthreads();
    if (threadIdx.x == 0) {
        __threadfence();
        atomicAdd(&g_barCnt, 1);
        while (atomicAdd(&g_barCnt, 0) < target) __nanosleep(64);
    }
    __syncthreads();
}

// ---------------- agg unit: 16 nodes, 256 threads (L2-coherent loads) ------
__device__ __forceinline__ void agg_unit(int u, int n, int wid, int lane) {
    int w   = u * 16 + wid * 2 + (lane >> 4);
    int l16 = lane & 15;
    if (w >= n) return;
    int beg = g_off[w], end = g_off[w + 1];
    uint4 outv;
    if (beg < end) {
        const uint4* hv = (const uint4*)g_fh;
        const uint32_t NEG = 0xFBFFFBFFu;        // half2(-65504,-65504)
        __half2 a0 = *(const __half2*)&NEG;
        __half2 a1 = a0, a2 = a0, a3 = a0;
        int j = beg;
        for (; j + 7 < end; j += 8) {
            int s0 = g_csr[j],     s1 = g_csr[j + 1];
            int s2 = g_csr[j + 2], s3 = g_csr[j + 3];
            int s4 = g_csr[j + 4], s5 = g_csr[j + 5];
            int s6 = g_csr[j + 6], s7 = g_csr[j + 7];
            uint4 v0 = __ldcg(hv + (size_t)s0 * 16 + l16);
            uint4 v1 = __ldcg(hv + (size_t)s1 * 16 + l16);
            uint4 v2 = __ldcg(hv + (size_t)s2 * 16 + l16);
            uint4 v3 = __ldcg(hv + (size_t)s3 * 16 + l16);
            uint4 v4 = __ldcg(hv + (size_t)s4 * 16 + l16);
            uint4 v5 = __ldcg(hv + (size_t)s5 * 16 + l16);
            uint4 v6 = __ldcg(hv + (size_t)s6 * 16 + l16);
            uint4 v7 = __ldcg(hv + (size_t)s7 * 16 + l16);
            __half2 m0x = __hmax2(__hmax2(*(__half2*)&v0.x, *(__half2*)&v1.x),
                                  __hmax2(*(__half2*)&v2.x, *(__half2*)&v3.x));
            __half2 m1x = __hmax2(__hmax2(*(__half2*)&v4.x, *(__half2*)&v5.x),
                                  __hmax2(*(__half2*)&v6.x, *(__half2*)&v7.x));
            __half2 m0y = __hmax2(__hmax2(*(__half2*)&v0.y, *(__half2*)&v1.y),
                                  __hmax2(*(__half2*)&v2.y, *(__half2*)&v3.y));
            __half2 m1y = __hmax2(__hmax2(*(__half2*)&v4.y, *(__half2*)&v5.y),
                                  __hmax2(*(__half2*)&v6.y, *(__half2*)&v7.y));
            __half2 m0z = __hmax2(__hmax2(*(__half2*)&v0.z, *(__half2*)&v1.z),
                                  __hmax2(*(__half2*)&v2.z, *(__half2*)&v3.z));
            __half2 m1z = __hmax2(__hmax2(*(__half2*)&v4.z, *(__half2*)&v5.z),
                                  __hmax2(*(__half2*)&v6.z, *(__half2*)&v7.z));
            __half2 m0w = __hmax2(__hmax2(*(__half2*)&v0.w, *(__half2*)&v1.w),
                                  __hmax2(*(__half2*)&v2.w, *(__half2*)&v3.w));
            __half2 m1w = __hmax2(__hmax2(*(__half2*)&v4.w, *(__half2*)&v5.w),
                                  __hmax2(*(__half2*)&v6.w, *(__half2*)&v7.w));
            a0 = __hmax2(a0, __hmax2(m0x, m1x));
            a1 = __hmax2(a1, __hmax2(m0y, m1y));
            a2 = __hmax2(a2, __hmax2(m0z, m1z));
            a3 = __hmax2(a3, __hmax2(m0w, m1w));
        }
        if (j + 3 < end) {
            int s0 = g_csr[j],     s1 = g_csr[j + 1];
            int s2 = g_csr[j + 2], s3 = g_csr[j + 3];
            uint4 v0 = __ldcg(hv + (size_t)s0 * 16 + l16);
            uint4 v1 = __ldcg(hv + (size_t)s1 * 16 + l16);
            uint4 v2 = __ldcg(hv + (size_t)s2 * 16 + l16);
            uint4 v3 = __ldcg(hv + (size_t)s3 * 16 + l16);
            a0 = __hmax2(a0, __hmax2(__hmax2(*(__half2*)&v0.x, *(__half2*)&v1.x),
                                     __hmax2(*(__half2*)&v2.x, *(__half2*)&v3.x)));
            a1 = __hmax2(a1, __hmax2(__hmax2(*(__half2*)&v0.y, *(__half2*)&v1.y),
                                     __hmax2(*(__half2*)&v2.y, *(__half2*)&v3.y)));
            a2 = __hmax2(a2, __hmax2(__hmax2(*(__half2*)&v0.z, *(__half2*)&v1.z),
                                     __hmax2(*(__half2*)&v2.z, *(__half2*)&v3.z)));
            a3 = __hmax2(a3, __hmax2(__hmax2(*(__half2*)&v0.w, *(__half2*)&v1.w),
                                     __hmax2(*(__half2*)&v2.w, *(__half2*)&v3.w)));
            j += 4;
        }
        for (; j < end; j++) {
            uint4 v0 = __ldcg(hv + (size_t)g_csr[j] * 16 + l16);
            a0 = __hmax2(a0, *(__half2*)&v0.x);
            a1 = __hmax2(a1, *(__half2*)&v0.y);
            a2 = __hmax2(a2, *(__half2*)&v0.z);
            a3 = __hmax2(a3, *(__half2*)&v0.w);
        }
        outv.x = *(uint32_t*)&a0;
        outv.y = *(uint32_t*)&a1;
        outv.z = *(uint32_t*)&a2;
        outv.w = *(uint32_t*)&a3;
    } else {
        outv = make_uint4(0, 0, 0, 0);   // empty segment -> 0 (PyG semantics)
    }
    ((uint4*)g_m)[(size_t)w * 16 + l16] = outv;
}

// ---------------- layer unit: 128-node tile GEMM+epilogue ------------------
#define FS_ST 20
#define WS_ST 20

__device__ __forceinline__ void layer_unit(
    int base, const float* __restrict__ bias, int has_res,
    const uint32_t* __restrict__ wh, int fuse,
    const float* __restrict__ Wo, const float* __restrict__ bo,
    float* __restrict__ outv, int n,
    uint32_t* Fs, uint32_t* Ws, float* sPart) {

    const int tid  = threadIdx.x;
    const int wid  = tid >> 5;
    const int lane = tid & 31;
    const int gi   = lane >> 2;
    const int ti   = lane & 3;
    const int wr   = wid & 3;
    const int wc   = wid >> 2;

    const int s_node = tid >> 1;
    const int s_half = tid & 1;
    const int gn_row = base + s_node;

    float acc[2][8][4];
#pragma unroll
    for (int mt = 0; mt < 2; mt++)
#pragma unroll
        for (int nt = 0; nt < 8; nt++)
#pragma unroll
            for (int q = 0; q < 4; q++) acc[mt][nt][q] = 0.f;

    uint4 pb0, pb1, pa0, pa1;
    {
        const uint4* bs = (const uint4*)(wh);
        pb0 = bs[tid];
        pb1 = bs[256 + tid];
        pa0 = make_uint4(0, 0, 0, 0); pa1 = pa0;
        if (gn_row < n) {
            const uint4* rp = (const uint4*)(g_m + (size_t)gn_row * HDIM + s_half * 16);
            pa0 = __ldcg(rp);
            pa1 = __ldcg(rp + 1);
        }
    }

    for (int kc = 0; kc < 8; kc++) {
        __syncthreads();
        {
            int col0 = tid >> 2, c40 = tid & 3;
            *(uint4*)&Ws[col0 * WS_ST + c40 * 4] = pb0;
            int lin1 = 256 + tid;
            int col1 = lin1 >> 2, c41 = lin1 & 3;
            *(uint4*)&Ws[col1 * WS_ST + c41 * 4] = pb1;
            uint32_t* fd = &Fs[s_node * FS_ST + s_half * 8];
            *(uint4*)fd       = pa0;
            *(uint4*)(fd + 4) = pa1;
        }
        __syncthreads();

        if (kc < 7) {
            int kn = kc + 1;
            const uint4* bs = (const uint4*)(wh + kn * 2048);
            pb0 = bs[tid];
            pb1 = bs[256 + tid];
            const __half* srcH = (kn < 4) ? g_m : g_fh;
            int k0 = (kn & 3) * 32;
            pa0 = make_uint4(0, 0, 0, 0); pa1 = pa0;
            if (gn_row < n) {
                const uint4* rp = (const uint4*)(srcH + (size_t)gn_row * HDIM + k0 + s_half * 16);
                pa0 = __ldcg(rp);
                pa1 = __ldcg(rp + 1);
            }
        }

#pragma unroll
        for (int ks = 0; ks < 2; ks++) {
            const int kb = ks * 8;
            uint32_t a[2][4];
#pragma unroll
            for (int mt = 0; mt < 2; mt++) {
                int rb = wr * 32 + mt * 16;
                a[mt][0] = Fs[(rb + gi)     * FS_ST + kb + ti];
                a[mt][1] = Fs[(rb + 8 + gi) * FS_ST + kb + ti];
                a[mt][2] = Fs[(rb + gi)     * FS_ST + kb + ti + 4];
                a[mt][3] = Fs[(rb + 8 + gi) * FS_ST + kb + ti + 4];
            }
#pragma unroll
            for (int nt = 0; nt < 8; nt++) {
                int cb = wc * 64 + nt * 8 + gi;
                uint32_t b0 = Ws[cb * WS_ST + kb + ti];
                uint32_t b1 = Ws[cb * WS_ST + kb + ti + 4];
                MMA_F16(acc[0][nt], a[0], b0, b1);
                MMA_F16(acc[1][nt], a[1], b0, b1);
            }
        }
    }

    float part[2][2] = {{0.f, 0.f}, {0.f, 0.f}};
#pragma unroll
    for (int nt = 0; nt < 8; nt++) {
        int col = wc * 64 + nt * 8 + ti * 2;
        float bb0 = bias[col], bb1 = bias[col + 1];
        float wo0 = 0.f, wo1 = 0.f;
        if (fuse) { wo0 = Wo[col]; wo1 = Wo[col + 1]; }
#pragma unroll
        for (int mt = 0; mt < 2; mt++) {
#pragma unroll
            for (int half = 0; half < 2; half++) {
                int row = base + wr * 32 + mt * 16 + gi + half * 8;
                if (row >= n) continue;
                float v0 = acc[mt][nt][half * 2 + 0] + bb0;
                float v1 = acc[mt][nt][half * 2 + 1] + bb1;
                v0 = (v0 > 0.f) ? v0 : expm1f(v0);
                v1 = (v1 > 0.f) ? v1 : expm1f(v1);
                size_t o = (size_t)row * HDIM + col;
                if (has_res) {
                    __half2 rh = __ldcg((const __half2*)(g_fh + o));
                    float2 rr = __half22float2(rh);
                    v0 += rr.x; v1 += rr.y;
                }
                if (fuse) {
                    part[mt][half] += v0 * wo0 + v1 * wo1;
                } else {
                    __half2 hv = __floats2half2_rn(v0, v1);
                    *(__half2*)(g_fh + o) = hv;
                }
            }
        }
    }

    if (fuse) {
#pragma unroll
        for (int mt = 0; mt < 2; mt++)
#pragma unroll
            for (int half = 0; half < 2; half++) {
                float p = part[mt][half];
                p += __shfl_xor_sync(0xffffffff, p, 1);
                p += __shfl_xor_sync(0xffffffff, p, 2);
                if (ti == 0) {
                    int rl = wr * 32 + mt * 16 + gi + half * 8;
                    sPart[rl * 2 + wc] = p;
                }
            }
        __syncthreads();
        if (tid < 128) {
            int row = base + tid;
            if (row < n) {
                float z = sPart[tid * 2] + sPart[tid * 2 + 1] + bo[0];
                outv[row] = 1.f / (1.f + expf(-z));
            }
        }
    }
}

// ---------------- persistent megakernel: 3 x (agg phase | layer phase) -----
__global__ void __launch_bounds__(256, 2) k_mega(
    const float* __restrict__ b1, const float* __restrict__ b2,
    const float* __restrict__ b3,
    const float* __restrict__ Wo, const float* __restrict__ bo,
    float* __restrict__ outv, int n) {
    __shared__ __align__(16) uint32_t Fs[128 * FS_ST];
    __shared__ __align__(16) uint32_t Ws[128 * WS_ST];
    __shared__ float sPart[128 * 2];

    const int wid  = threadIdx.x >> 5;
    const int lane = threadIdx.x & 31;
    const int nB   = gridDim.x;
    const int aggUnits   = (n + 15) >> 4;
    const int layerUnits = (n + 127) >> 7;
    int phase = 0;

    for (int l = 0; l < 3; l++) {
        // ---- agg phase ----
        for (int u = blockIdx.x; u < aggUnits; u += nB)
            agg_unit(u, n, wid, lane);
        grid_bar(nB * (++phase));

        // ---- layer phase ----
        const float* bias = (l == 0) ? b1 : (l == 1) ? b2 : b3;
        const uint32_t* wh = g_Wh + l * 16384;
        int has_res = (l > 0);
        int fuse    = (l == 2);
        for (int u = blockIdx.x; u < layerUnits; u += nB)
            layer_unit(u * 128, bias, has_res, wh, fuse, Wo, bo, outv, n,
                       Fs, Ws, sPart);
        if (l < 2) grid_bar(nB * (++phase));
    }
}

// ---------------- launcher (kernel launches ONLY) ---------------------------
extern "C" void kernel_launch(void* const* d_in, const int* in_sizes, int n_in,
                              void* d_out, int out_size) {
    const float* x   = (const float*)d_in[0];
    const int*   ei  = (const int*)d_in[1];     // edge_index is int32
    const float* W1l = (const float*)d_in[2];
    const float* b1  = (const float*)d_in[3];
    const float* W1r = (const float*)d_in[4];
    const float* W2l = (const float*)d_in[5];
    const float* b2  = (const float*)d_in[6];
    const float* W2r = (const float*)d_in[7];
    const float* W3l = (const float*)d_in[8];
    const float* b3  = (const float*)d_in[9];
    const float* W3r = (const float*)d_in[10];
    const float* Wo  = (const float*)d_in[11];
    const float* bo  = (const float*)d_in[12];
    float* out = (float*)d_out;

    int N = in_sizes[0] / HDIM;
    int E = in_sizes[1] / 2;
    if (N > NMAX) N = NMAX;
    if (E > EMAX) E = EMAX;

    int total4 = N * HDIM / 4;

    // ---- setup: zeroing, x->fp16, weight prep, barrier reset ----
    k_setup<<<(total4 + 255) / 256, 256>>>(x, W1l, W1r, W2l, W2r, W3l, W3r, N, total4);

    // ---- CSR build ----
    int eThreads = (E + 3) / 4;
    k_hist    <<<(eThreads + 255) / 256, 256>>>(ei, E, N);
    int nb = N / 1024 + 1;
    k_scan_all<<<nb, 1024>>>(N, E);
    k_fill    <<<(E + 255) / 256, 256>>>(ei, E, N);

    // ---- persistent fused GNN: 3 x (agg | GEMM+epilogue), grid barriers ----
    k_mega<<<NPBLK, 256>>>(b1, b2, b3, Wo, bo, out, N);
}

// round 15
// speedup vs baseline: 1.2309x; 1.2309x over previous
#include <cuda_runtime.h>
#include <cuda_fp16.h>
#include <math.h>
#include <stdint.h>

#define NMAX 100000
#define EMAX 1600000
#define HDIM 128

// ---------------- scratch (device globals; referenced by name only) --------
__device__ __align__(16) __half g_m [NMAX * HDIM];   // aggregated max (fp16)
__device__ __align__(16) __half g_fh[NMAX * HDIM];   // current layer state (fp16)
__device__ int   g_deg[NMAX];
__device__ int   g_off[NMAX + 1];
__device__ int   g_cur[NMAX];
__device__ int   g_csr[EMAX];
__device__ int   g_bsum[128];
__device__ int   g_flag[128];
// fp16 weights in mma-ready layout: [3][8 kc][128 col][16 half2]
__device__ __align__(16) uint32_t g_Wh[3 * 8 * 128 * 16];

#define MMA_F16(d, a, b0v, b1v) \
    asm volatile( \
        "mma.sync.aligned.m16n8k16.row.col.f32.f16.f16.f32 " \
        "{%0,%1,%2,%3}, {%4,%5,%6,%7}, {%8,%9}, {%0,%1,%2,%3};" \
        : "+f"((d)[0]), "+f"((d)[1]), "+f"((d)[2]), "+f"((d)[3]) \
        : "r"((a)[0]), "r"((a)[1]), "r"((a)[2]), "r"((a)[3]), \
          "r"(b0v), "r"(b1v))

// ---------------- fused setup: deg/flag=0, x->fp16 mirror, weight prep -----
__global__ void k_setup(const float* __restrict__ x,
                        const float* __restrict__ W1l, const float* __restrict__ W1r,
                        const float* __restrict__ W2l, const float* __restrict__ W2r,
                        const float* __restrict__ W3l, const float* __restrict__ W3r,
                        int n, int total4) {
    int i = blockIdx.x * blockDim.x + threadIdx.x;
    if (i < total4) {
        float4 f = ((const float4*)x)[i];
        __half2 h0 = __floats2half2_rn(f.x, f.y);
        __half2 h1 = __floats2half2_rn(f.z, f.w);
        uint2 u;
        u.x = *(uint32_t*)&h0;
        u.y = *(uint32_t*)&h1;
        ((uint2*)g_fh)[i] = u;
    }
    if (i < n) g_deg[i] = 0;
    if (i < 128) g_flag[i] = 0;
    if (i < 3 * 8 * 128 * 16) {
        int widx = i >> 14;
        int rem  = i & 16383;
        int kc   = rem >> 11;
        int rem2 = rem & 2047;
        int col  = rem2 >> 4;
        int hp   = rem2 & 15;
        int k    = kc * 32 + hp * 2;
        const float* Wl = (widx == 0) ? W1l : (widx == 1) ? W2l : W3l;
        const float* Wr = (widx == 0) ? W1r : (widx == 1) ? W2r : W3r;
        float v0 = (k < HDIM)     ? Wl[col * HDIM + k]     : Wr[col * HDIM + k - HDIM];
        float v1 = (k + 1 < HDIM) ? Wl[col * HDIM + k + 1] : Wr[col * HDIM + k + 1 - HDIM];
        __half2 h = __floats2half2_rn(v0, v1);
        g_Wh[i] = *(uint32_t*)&h;
    }
}

// ---------------- CSR build (hist: 4 edges/thread; fill: scalar) -----------
__global__ void k_hist(const int* __restrict__ ei, int E, int n) {
    int t  = blockIdx.x * blockDim.x + threadIdx.x;
    int e4 = t * 4;
    if (e4 + 3 < E) {
        int4 d = *(const int4*)(ei + E + e4);
        if ((unsigned)d.x < (unsigned)n) atomicAdd(&g_deg[d.x], 1);
        if ((unsigned)d.y < (unsigned)n) atomicAdd(&g_deg[d.y], 1);
        if ((unsigned)d.z < (unsigned)n) atomicAdd(&g_deg[d.z], 1);
        if ((unsigned)d.w < (unsigned)n) atomicAdd(&g_deg[d.w], 1);
    } else {
        for (int e = e4; e < E; e++) {
            int d = ei[E + e];
            if ((unsigned)d < (unsigned)n) atomicAdd(&g_deg[d], 1);
        }
    }
}

// single-kernel exclusive scan (all blocks resident; parallel aggregate read)
__global__ void k_scan_all(int n, int E) {
    __shared__ int s[1024];
    __shared__ int s2[1024];
    int tid = threadIdx.x;
    int bid = blockIdx.x;
    int gid = bid * 1024 + tid;
    int v = (gid < n) ? g_deg[gid] : 0;
    s[tid] = v;
    __syncthreads();
    for (int d = 1; d < 1024; d <<= 1) {
        int t = (tid >= d) ? s[tid - d] : 0;
        __syncthreads();
        s[tid] += t;
        __syncthreads();
    }
    if (tid == 0) {
        g_bsum[bid] = s[1023];
        __threadfence();
        atomicExch(&g_flag[bid], 1);
    }
    int pv = 0;
    if (tid < bid) {
        while (atomicAdd(&g_flag[tid], 0) == 0) {}
        pv = atomicAdd(&g_bsum[tid], 0);
    }
    s2[tid] = pv;
    __syncthreads();
    for (int d = 512; d > 0; d >>= 1) {
        if (tid < d) s2[tid] += s2[tid + d];
        __syncthreads();
    }
    int prefix = s2[0];
    if (gid < n) {
        int o = s[tid] - v + prefix;
        g_off[gid] = o;
        g_cur[gid] = o;
    } else if (gid == n) {
        g_off[n] = E;
    }
}

// scalar fill (measured faster than int4 variant: 23.7 vs 26.8 us)
__global__ void k_fill(const int* __restrict__ ei, int E, int n) {
    int e = blockIdx.x * blockDim.x + threadIdx.x;
    if (e < E) {
        int s = ei[e];
        int d = ei[E + e];
        if ((unsigned)s < (unsigned)n && (unsigned)d < (unsigned)n) {
            int pos = atomicAdd(&g_cur[d], 1);
            if ((unsigned)pos < (unsigned)E) g_csr[pos] = s;
        }
    }
}

// ---------------- per-node max aggregation (2 nodes/warp, uint4, MLP=8) ----
__global__ void k_agg(int n) {
    int gw   = (blockIdx.x * blockDim.x + threadIdx.x) >> 5;
    int lane = threadIdx.x & 31;
    int w    = gw * 2 + (lane >> 4);
    int l16  = lane & 15;
    if (w >= n) return;
    int beg = g_off[w], end = g_off[w + 1];
    uint4 outv;
    if (beg < end) {
        const uint4* hv = (const uint4*)g_fh;    // row = 16 uint4
        const uint32_t NEG = 0xFBFFFBFFu;        // half2(-65504,-65504)
        __half2 a0 = *(const __half2*)&NEG;
        __half2 a1 = a0, a2 = a0, a3 = a0;
        int j = beg;
        for (; j + 7 < end; j += 8) {
            int s0 = g_csr[j],     s1 = g_csr[j + 1];
            int s2 = g_csr[j + 2], s3 = g_csr[j + 3];
            int s4 = g_csr[j + 4], s5 = g_csr[j + 5];
            int s6 = g_csr[j + 6], s7 = g_csr[j + 7];
            uint4 v0 = hv[(size_t)s0 * 16 + l16];
            uint4 v1 = hv[(size_t)s1 * 16 + l16];
            uint4 v2 = hv[(size_t)s2 * 16 + l16];
            uint4 v3 = hv[(size_t)s3 * 16 + l16];
            uint4 v4 = hv[(size_t)s4 * 16 + l16];
            uint4 v5 = hv[(size_t)s5 * 16 + l16];
            uint4 v6 = hv[(size_t)s6 * 16 + l16];
            uint4 v7 = hv[(size_t)s7 * 16 + l16];
            __half2 m0x = __hmax2(__hmax2(*(__half2*)&v0.x, *(__half2*)&v1.x),
                                  __hmax2(*(__half2*)&v2.x, *(__half2*)&v3.x));
            __half2 m1x = __hmax2(__hmax2(*(__half2*)&v4.x, *(__half2*)&v5.x),
                                  __hmax2(*(__half2*)&v6.x, *(__half2*)&v7.x));
            __half2 m0y = __hmax2(__hmax2(*(__half2*)&v0.y, *(__half2*)&v1.y),
                                  __hmax2(*(__half2*)&v2.y, *(__half2*)&v3.y));
            __half2 m1y = __hmax2(__hmax2(*(__half2*)&v4.y, *(__half2*)&v5.y),
                                  __hmax2(*(__half2*)&v6.y, *(__half2*)&v7.y));
            __half2 m0z = __hmax2(__hmax2(*(__half2*)&v0.z, *(__half2*)&v1.z),
                                  __hmax2(*(__half2*)&v2.z, *(__half2*)&v3.z));
            __half2 m1z = __hmax2(__hmax2(*(__half2*)&v4.z, *(__half2*)&v5.z),
                                  __hmax2(*(__half2*)&v6.z, *(__half2*)&v7.z));
            __half2 m0w = __hmax2(__hmax2(*(__half2*)&v0.w, *(__half2*)&v1.w),
                                  __hmax2(*(__half2*)&v2.w, *(__half2*)&v3.w));
            __half2 m1w = __hmax2(__hmax2(*(__half2*)&v4.w, *(__half2*)&v5.w),
                                  __hmax2(*(__half2*)&v6.w, *(__half2*)&v7.w));
            a0 = __hmax2(a0, __hmax2(m0x, m1x));
            a1 = __hmax2(a1, __hmax2(m0y, m1y));
            a2 = __hmax2(a2, __hmax2(m0z, m1z));
            a3 = __hmax2(a3, __hmax2(m0w, m1w));
        }
        if (j + 3 < end) {
            int s0 = g_csr[j],     s1 = g_csr[j + 1];
            int s2 = g_csr[j + 2], s3 = g_csr[j + 3];
            uint4 v0 = hv[(size_t)s0 * 16 + l16];
            uint4 v1 = hv[(size_t)s1 * 16 + l16];
            uint4 v2 = hv[(size_t)s2 * 16 + l16];
            uint4 v3 = hv[(size_t)s3 * 16 + l16];
            a0 = __hmax2(a0, __hmax2(__hmax2(*(__half2*)&v0.x, *(__half2*)&v1.x),
                                     __hmax2(*(__half2*)&v2.x, *(__half2*)&v3.x)));
            a1 = __hmax2(a1, __hmax2(__hmax2(*(__half2*)&v0.y, *(__half2*)&v1.y),
                                     __hmax2(*(__half2*)&v2.y, *(__half2*)&v3.y)));
            a2 = __hmax2(a2, __hmax2(__hmax2(*(__half2*)&v0.z, *(__half2*)&v1.z),
                                     __hmax2(*(__half2*)&v2.z, *(__half2*)&v3.z)));
            a3 = __hmax2(a3, __hmax2(__hmax2(*(__half2*)&v0.w, *(__half2*)&v1.w),
                                     __hmax2(*(__half2*)&v2.w, *(__half2*)&v3.w)));
            j += 4;
        }
        for (; j < end; j++) {
            uint4 v0 = hv[(size_t)g_csr[j] * 16 + l16];
            a0 = __hmax2(a0, *(__half2*)&v0.x);
            a1 = __hmax2(a1, *(__half2*)&v0.y);
            a2 = __hmax2(a2, *(__half2*)&v0.z);
            a3 = __hmax2(a3, *(__half2*)&v0.w);
        }
        outv.x = *(uint32_t*)&a0;
        outv.y = *(uint32_t*)&a1;
        outv.z = *(uint32_t*)&a2;
        outv.w = *(uint32_t*)&a3;
    } else {
        outv = make_uint4(0, 0, 0, 0);   // empty segment -> 0 (PyG semantics)
    }
    ((uint4*)g_m)[(size_t)w * 16 + l16] = outv;
}

// ---------------- fp16 mma layer: GEMM + bias + ELU + residual (+head) -----
// new_h[i,:] = elu( [m|fh][i,:] @ Wcat^T + b ) (+ fh)  -> written back to fh
// fuse=1: instead of storing, compute sigmoid(h3 . Wo + bo) -> outv
#define FS_ST 20
#define WS_ST 20

__global__ void __launch_bounds__(256, 2) k_layer_mma(
    const float* __restrict__ bias, int has_res, int wsel,
    int fuse,
    const float* __restrict__ Wo, const float* __restrict__ bo,
    float* __restrict__ outv, int n) {
    __shared__ __align__(16) uint32_t Fs[128 * FS_ST];
    __shared__ __align__(16) uint32_t Ws[128 * WS_ST];
    __shared__ float sPart[128 * 2];

    const uint32_t* wh = g_Wh + wsel * 16384;

    const int tid  = threadIdx.x;
    const int wid  = tid >> 5;
    const int lane = tid & 31;
    const int gi   = lane >> 2;
    const int ti   = lane & 3;
    const int wr   = wid & 3;     // rows wr*32..+31
    const int wc   = wid >> 2;    // cols wc*64..+63
    const int base = blockIdx.x * 128;

    const int s_node = tid >> 1;
    const int s_half = tid & 1;
    const int gn_row = base + s_node;

    float acc[2][8][4];
#pragma unroll
    for (int mt = 0; mt < 2; mt++)
#pragma unroll
        for (int nt = 0; nt < 8; nt++)
#pragma unroll
            for (int q = 0; q < 4; q++) acc[mt][nt][q] = 0.f;

    uint4 pb0, pb1, pa0, pa1;
    // prefetch chunk 0
    {
        const uint4* bs = (const uint4*)(wh);
        pb0 = bs[tid];
        pb1 = bs[256 + tid];
        pa0 = make_uint4(0, 0, 0, 0); pa1 = pa0;
        if (gn_row < n) {
            const __half* rp = g_m + (size_t)gn_row * HDIM + s_half * 16;
            pa0 = *(const uint4*)rp;
            pa1 = *(const uint4*)(rp + 8);
        }
    }

    for (int kc = 0; kc < 8; kc++) {
        __syncthreads();   // smem free (prev chunk consumed)
        // store prefetched chunk
        {
            int col0 = tid >> 2, c40 = tid & 3;
            *(uint4*)&Ws[col0 * WS_ST + c40 * 4] = pb0;
            int lin1 = 256 + tid;
            int col1 = lin1 >> 2, c41 = lin1 & 3;
            *(uint4*)&Ws[col1 * WS_ST + c41 * 4] = pb1;
            uint32_t* fd = &Fs[s_node * FS_ST + s_half * 8];
            *(uint4*)fd       = pa0;
            *(uint4*)(fd + 4) = pa1;
        }
        __syncthreads();   // smem ready

        // prefetch next chunk (latency overlaps MMA below)
        if (kc < 7) {
            int kn = kc + 1;
            const uint4* bs = (const uint4*)(wh + kn * 2048);
            pb0 = bs[tid];
            pb1 = bs[256 + tid];
            const __half* srcH = (kn < 4) ? g_m : g_fh;
            int k0 = (kn & 3) * 32;
            pa0 = make_uint4(0, 0, 0, 0); pa1 = pa0;
            if (gn_row < n) {
                const __half* rp = srcH + (size_t)gn_row * HDIM + k0 + s_half * 16;
                pa0 = *(const uint4*)rp;
                pa1 = *(const uint4*)(rp + 8);
            }
        }

#pragma unroll
        for (int ks = 0; ks < 2; ks++) {
            const int kb = ks * 8;
            uint32_t a[2][4];
#pragma unroll
            for (int mt = 0; mt < 2; mt++) {
                int rb = wr * 32 + mt * 16;
                a[mt][0] = Fs[(rb + gi)     * FS_ST + kb + ti];
                a[mt][1] = Fs[(rb + 8 + gi) * FS_ST + kb + ti];
                a[mt][2] = Fs[(rb + gi)     * FS_ST + kb + ti + 4];
                a[mt][3] = Fs[(rb + 8 + gi) * FS_ST + kb + ti + 4];
            }
#pragma unroll
            for (int nt = 0; nt < 8; nt++) {
                int cb = wc * 64 + nt * 8 + gi;
                uint32_t b0 = Ws[cb * WS_ST + kb + ti];
                uint32_t b1 = Ws[cb * WS_ST + kb + ti + 4];
                MMA_F16(acc[0][nt], a[0], b0, b1);
                MMA_F16(acc[1][nt], a[1], b0, b1);
            }
        }
    }

    // ---------------- epilogue ----------------
    float part[2][2] = {{0.f, 0.f}, {0.f, 0.f}};
#pragma unroll
    for (int nt = 0; nt < 8; nt++) {
        int col = wc * 64 + nt * 8 + ti * 2;
        float bb0 = bias[col], bb1 = bias[col + 1];
        float wo0 = 0.f, wo1 = 0.f;
        if (fuse) { wo0 = Wo[col]; wo1 = Wo[col + 1]; }
#pragma unroll
        for (int mt = 0; mt < 2; mt++) {
#pragma unroll
            for (int half = 0; half < 2; half++) {
                int row = base + wr * 32 + mt * 16 + gi + half * 8;
                if (row >= n) continue;
                float v0 = acc[mt][nt][half * 2 + 0] + bb0;
                float v1 = acc[mt][nt][half * 2 + 1] + bb1;
                v0 = (v0 > 0.f) ? v0 : expm1f(v0);
                v1 = (v1 > 0.f) ? v1 : expm1f(v1);
                size_t o = (size_t)row * HDIM + col;
                if (has_res) {
                    __half2 rh = *(const __half2*)(g_fh + o);
                    float2 rr = __half22float2(rh);
                    v0 += rr.x; v1 += rr.y;
                }
                if (fuse) {
                    part[mt][half] += v0 * wo0 + v1 * wo1;
                } else {
                    __half2 hv = __floats2half2_rn(v0, v1);
                    *(__half2*)(g_fh + o) = hv;
                }
            }
        }
    }

    if (fuse) {
#pragma unroll
        for (int mt = 0; mt < 2; mt++)
#pragma unroll
            for (int half = 0; half < 2; half++) {
                float p = part[mt][half];
                p += __shfl_xor_sync(0xffffffff, p, 1);
                p += __shfl_xor_sync(0xffffffff, p, 2);
                if (ti == 0) {
                    int rl = wr * 32 + mt * 16 + gi + half * 8;
                    sPart[rl * 2 + wc] = p;
                }
            }
        __syncthreads();
        if (tid < 128) {
            int row = base + tid;
            if (row < n) {
                float z = sPart[tid * 2] + sPart[tid * 2 + 1] + bo[0];
                outv[row] = 1.f / (1.f + expf(-z));
            }
        }
    }
}

// ---------------- launcher (kernel launches ONLY) ---------------------------
extern "C" void kernel_launch(void* const* d_in, const int* in_sizes, int n_in,
                              void* d_out, int out_size) {
    const float* x   = (const float*)d_in[0];
    const int*   ei  = (const int*)d_in[1];     // edge_index is int32
    const float* W1l = (const float*)d_in[2];
    const float* b1  = (const float*)d_in[3];
    const float* W1r = (const float*)d_in[4];
    const float* W2l = (const float*)d_in[5];
    const float* b2  = (const float*)d_in[6];
    const float* W2r = (const float*)d_in[7];
    const float* W3l = (const float*)d_in[8];
    const float* b3  = (const float*)d_in[9];
    const float* W3r = (const float*)d_in[10];
    const float* Wo  = (const float*)d_in[11];
    const float* bo  = (const float*)d_in[12];
    float* out = (float*)d_out;

    int N = in_sizes[0] / HDIM;
    int E = in_sizes[1] / 2;
    if (N > NMAX) N = NMAX;
    if (E > EMAX) E = EMAX;

    int total4 = N * HDIM / 4;

    // ---- fused setup: deg/flag=0, x->fp16, weight prep ----
    k_setup<<<(total4 + 255) / 256, 256>>>(x, W1l, W1r, W2l, W2r, W3l, W3r, N, total4);

    // ---- CSR build (dst-sorted adjacency) ----
    int eThreads = (E + 3) / 4;
    k_hist    <<<(eThreads + 255) / 256, 256>>>(ei, E, N);
    int nb = N / 1024 + 1;
    k_scan_all<<<nb, 1024>>>(N, E);
    k_fill    <<<(E + 255) / 256, 256>>>(ei, E, N);

    int aggBlocks   = (N * 16 + 255) / 256;
    int layerBlocks = (N + 127) / 128;

    // ---- layer 1: agg(x) -> GEMM -> fh = h1 ----
    k_agg      <<<aggBlocks, 256>>>(N);
    k_layer_mma<<<layerBlocks, 256>>>(b1, 0, 0, 0,
                                      (const float*)0, (const float*)0, (float*)0, N);

    // ---- layer 2: agg(h1) -> GEMM + residual -> fh = h2 ----
    k_agg      <<<aggBlocks, 256>>>(N);
    k_layer_mma<<<layerBlocks, 256>>>(b2, 1, 1, 0,
                                      (const float*)0, (const float*)0, (float*)0, N);

    // ---- layer 3: agg(h2) -> GEMM + residual + fused sigmoid head -> out ----
    k_agg      <<<aggBlocks, 256>>>(N);
    k_layer_mma<<<layerBlocks, 256>>>(b3, 1, 2, 1, Wo, bo, out, N);
}

// round 17
// speedup vs baseline: 1.2662x; 1.0286x over previous
#include <cuda_runtime.h>
#include <cuda_fp16.h>
#include <math.h>
#include <stdint.h>

#define NMAX 100000
#define EMAX 1600000
#define HDIM 128

// ---------------- scratch (device globals; referenced by name only) --------
__device__ __align__(16) __half g_m [NMAX * HDIM];   // aggregated max (fp16)
__device__ __align__(16) __half g_fh[NMAX * HDIM];   // current layer state (fp16)
__device__ int   g_deg[NMAX];     // zero at load; re-zeroed by k_scan_all each call
__device__ int   g_off[NMAX + 1];
__device__ int   g_cur[NMAX];
__device__ int   g_csr[EMAX];
__device__ int   g_bsum[128];
__device__ int   g_flag[128];
// fp16 weights in mma-ready layout: [3][4 kc64][128 col][32 half2]
__device__ __align__(16) uint32_t g_Wh[3 * 4 * 128 * 32];

#define MMA_F16(d, a, b0v, b1v) \
    asm volatile( \
        "mma.sync.aligned.m16n8k16.row.col.f32.f16.f16.f32 " \
        "{%0,%1,%2,%3}, {%4,%5,%6,%7}, {%8,%9}, {%0,%1,%2,%3};" \
        : "+f"((d)[0]), "+f"((d)[1]), "+f"((d)[2]), "+f"((d)[3]) \
        : "r"((a)[0]), "r"((a)[1]), "r"((a)[2]), "r"((a)[3]), \
          "r"(b0v), "r"(b1v))

// ---------------- fused setup: x->fp16, weight prep, flag reset, HIST ------
// relies on g_deg == 0 on entry (module-load zero; k_scan_all re-zeroes)
__global__ void k_setup(const float* __restrict__ x, const int* __restrict__ ei,
                        const float* __restrict__ W1l, const float* __restrict__ W1r,
                        const float* __restrict__ W2l, const float* __restrict__ W2r,
                        const float* __restrict__ W3l, const float* __restrict__ W3r,
                        int n, int total4, int E) {
    int i = blockIdx.x * blockDim.x + threadIdx.x;
    if (i < total4) {
        float4 f = ((const float4*)x)[i];
        __half2 h0 = __floats2half2_rn(f.x, f.y);
        __half2 h1 = __floats2half2_rn(f.z, f.w);
        uint2 u;
        u.x = *(uint32_t*)&h0;
        u.y = *(uint32_t*)&h1;
        ((uint2*)g_fh)[i] = u;
    }
    if (i < 128) g_flag[i] = 0;
    // histogram: 4 edges per thread
    int e4 = i * 4;
    if (e4 < E) {
        if (e4 + 3 < E) {
            int4 d = *(const int4*)(ei + E + e4);
            if ((unsigned)d.x < (unsigned)n) atomicAdd(&g_deg[d.x], 1);
            if ((unsigned)d.y < (unsigned)n) atomicAdd(&g_deg[d.y], 1);
            if ((unsigned)d.z < (unsigned)n) atomicAdd(&g_deg[d.z], 1);
            if ((unsigned)d.w < (unsigned)n) atomicAdd(&g_deg[d.w], 1);
        } else {
            for (int e = e4; e < E; e++) {
                int d = ei[E + e];
                if ((unsigned)d < (unsigned)n) atomicAdd(&g_deg[d], 1);
            }
        }
    }
    // weight prep: [widx][kc64][col][hp32] half2, k = kc64*64 + hp*2
    if (i < 3 * 4 * 128 * 32) {
        int widx = i >> 14;
        int rem  = i & 16383;
        int kc   = rem >> 12;         // 0..3
        int rem2 = rem & 4095;
        int col  = rem2 >> 5;         // 0..127
        int hp   = rem2 & 31;         // 0..31
        int k    = kc * 64 + hp * 2;
        const float* Wl = (widx == 0) ? W1l : (widx == 1) ? W2l : W3l;
        const float* Wr = (widx == 0) ? W1r : (widx == 1) ? W2r : W3r;
        float v0 = (k < HDIM)     ? Wl[col * HDIM + k]     : Wr[col * HDIM + k - HDIM];
        float v1 = (k + 1 < HDIM) ? Wl[col * HDIM + k + 1] : Wr[col * HDIM + k + 1 - HDIM];
        __half2 h = __floats2half2_rn(v0, v1);
        g_Wh[i] = *(uint32_t*)&h;
    }
}

// single-kernel exclusive scan; re-zeroes g_deg for next call
__global__ void k_scan_all(int n, int E) {
    __shared__ int s[1024];
    __shared__ int s2[1024];
    int tid = threadIdx.x;
    int bid = blockIdx.x;
    int gid = bid * 1024 + tid;
    int v = (gid < n) ? g_deg[gid] : 0;
    if (gid < n) g_deg[gid] = 0;          // reset for next call's fused hist
    s[tid] = v;
    __syncthreads();
    for (int d = 1; d < 1024; d <<= 1) {
        int t = (tid >= d) ? s[tid - d] : 0;
        __syncthreads();
        s[tid] += t;
        __syncthreads();
    }
    if (tid == 0) {
        g_bsum[bid] = s[1023];
        __threadfence();
        atomicExch(&g_flag[bid], 1);
    }
    int pv = 0;
    if (tid < bid) {
        while (atomicAdd(&g_flag[tid], 0) == 0) {}
        pv = atomicAdd(&g_bsum[tid], 0);
    }
    s2[tid] = pv;
    __syncthreads();
    for (int d = 512; d > 0; d >>= 1) {
        if (tid < d) s2[tid] += s2[tid + d];
        __syncthreads();
    }
    int prefix = s2[0];
    if (gid < n) {
        int o = s[tid] - v + prefix;
        g_off[gid] = o;
        g_cur[gid] = o;
    } else if (gid == n) {
        g_off[n] = E;
    }
}

// scalar fill (measured faster than int4 variant: 23.7 vs 26.8 us)
__global__ void k_fill(const int* __restrict__ ei, int E, int n) {
    int e = blockIdx.x * blockDim.x + threadIdx.x;
    if (e < E) {
        int s = ei[e];
        int d = ei[E + e];
        if ((unsigned)s < (unsigned)n && (unsigned)d < (unsigned)n) {
            int pos = atomicAdd(&g_cur[d], 1);
            if ((unsigned)pos < (unsigned)E) g_csr[pos] = s;
        }
    }
}

// ---------------- per-node max aggregation (2 nodes/warp, uint4, MLP=8) ----
__global__ void k_agg(int n) {
    int gw   = (blockIdx.x * blockDim.x + threadIdx.x) >> 5;
    int lane = threadIdx.x & 31;
    int w    = gw * 2 + (lane >> 4);
    int l16  = lane & 15;
    if (w >= n) return;
    int beg = g_off[w], end = g_off[w + 1];
    uint4 outv;
    if (beg < end) {
        const uint4* hv = (const uint4*)g_fh;    // row = 16 uint4
        const uint32_t NEG = 0xFBFFFBFFu;        // half2(-65504,-65504)
        __half2 a0 = *(const __half2*)&NEG;
        __half2 a1 = a0, a2 = a0, a3 = a0;
        int j = beg;
        for (; j + 7 < end; j += 8) {
            int s0 = g_csr[j],     s1 = g_csr[j + 1];
            int s2 = g_csr[j + 2], s3 = g_csr[j + 3];
            int s4 = g_csr[j + 4], s5 = g_csr[j + 5];
            int s6 = g_csr[j + 6], s7 = g_csr[j + 7];
            uint4 v0 = hv[(size_t)s0 * 16 + l16];
            uint4 v1 = hv[(size_t)s1 * 16 + l16];
            uint4 v2 = hv[(size_t)s2 * 16 + l16];
            uint4 v3 = hv[(size_t)s3 * 16 + l16];
            uint4 v4 = hv[(size_t)s4 * 16 + l16];
            uint4 v5 = hv[(size_t)s5 * 16 + l16];
            uint4 v6 = hv[(size_t)s6 * 16 + l16];
            uint4 v7 = hv[(size_t)s7 * 16 + l16];
            __half2 m0x = __hmax2(__hmax2(*(__half2*)&v0.x, *(__half2*)&v1.x),
                                  __hmax2(*(__half2*)&v2.x, *(__half2*)&v3.x));
            __half2 m1x = __hmax2(__hmax2(*(__half2*)&v4.x, *(__half2*)&v5.x),
                                  __hmax2(*(__half2*)&v6.x, *(__half2*)&v7.x));
            __half2 m0y = __hmax2(__hmax2(*(__half2*)&v0.y, *(__half2*)&v1.y),
                                  __hmax2(*(__half2*)&v2.y, *(__half2*)&v3.y));
            __half2 m1y = __hmax2(__hmax2(*(__half2*)&v4.y, *(__half2*)&v5.y),
                                  __hmax2(*(__half2*)&v6.y, *(__half2*)&v7.y));
            __half2 m0z = __hmax2(__hmax2(*(__half2*)&v0.z, *(__half2*)&v1.z),
                                  __hmax2(*(__half2*)&v2.z, *(__half2*)&v3.z));
            __half2 m1z = __hmax2(__hmax2(*(__half2*)&v4.z, *(__half2*)&v5.z),
                                  __hmax2(*(__half2*)&v6.z, *(__half2*)&v7.z));
            __half2 m0w = __hmax2(__hmax2(*(__half2*)&v0.w, *(__half2*)&v1.w),
                                  __hmax2(*(__half2*)&v2.w, *(__half2*)&v3.w));
            __half2 m1w = __hmax2(__hmax2(*(__half2*)&v4.w, *(__half2*)&v5.w),
                                  __hmax2(*(__half2*)&v6.w, *(__half2*)&v7.w));
            a0 = __hmax2(a0, __hmax2(m0x, m1x));
            a1 = __hmax2(a1, __hmax2(m0y, m1y));
            a2 = __hmax2(a2, __hmax2(m0z, m1z));
            a3 = __hmax2(a3, __hmax2(m0w, m1w));
        }
        if (j + 3 < end) {
            int s0 = g_csr[j],     s1 = g_csr[j + 1];
            int s2 = g_csr[j + 2], s3 = g_csr[j + 3];
            uint4 v0 = hv[(size_t)s0 * 16 + l16];
            uint4 v1 = hv[(size_t)s1 * 16 + l16];
            uint4 v2 = hv[(size_t)s2 * 16 + l16];
            uint4 v3 = hv[(size_t)s3 * 16 + l16];
            a0 = __hmax2(a0, __hmax2(__hmax2(*(__half2*)&v0.x, *(__half2*)&v1.x),
                                     __hmax2(*(__half2*)&v2.x, *(__half2*)&v3.x)));
            a1 = __hmax2(a1, __hmax2(__hmax2(*(__half2*)&v0.y, *(__half2*)&v1.y),
                                     __hmax2(*(__half2*)&v2.y, *(__half2*)&v3.y)));
            a2 = __hmax2(a2, __hmax2(__hmax2(*(__half2*)&v0.z, *(__half2*)&v1.z),
                                     __hmax2(*(__half2*)&v2.z, *(__half2*)&v3.z)));
            a3 = __hmax2(a3, __hmax2(__hmax2(*(__half2*)&v0.w, *(__half2*)&v1.w),
                                     __hmax2(*(__half2*)&v2.w, *(__half2*)&v3.w)));
            j += 4;
        }
        for (; j < end; j++) {
            uint4 v0 = hv[(size_t)g_csr[j] * 16 + l16];
            a0 = __hmax2(a0, *(__half2*)&v0.x);
            a1 = __hmax2(a1, *(__half2*)&v0.y);
            a2 = __hmax2(a2, *(__half2*)&v0.z);
            a3 = __hmax2(a3, *(__half2*)&v0.w);
        }
        outv.x = *(uint32_t*)&a0;
        outv.y = *(uint32_t*)&a1;
        outv.z = *(uint32_t*)&a2;
        outv.w = *(uint32_t*)&a3;
    } else {
        outv = make_uint4(0, 0, 0, 0);   // empty segment -> 0 (PyG semantics)
    }
    ((uint4*)g_m)[(size_t)w * 16 + l16] = outv;
}

// ---------------- fp16 mma layer: K=64 chunks (4 total), GEMM + epilogue ---
// new_h[i,:] = elu( [m|fh][i,:] @ Wcat^T + b ) (+ fh)  -> written back to fh
// fuse=1: compute sigmoid(h3 . Wo + bo) -> outv instead of storing
#define FS_ST 36
#define WS_ST 36

__global__ void __launch_bounds__(256, 2) k_layer_mma(
    const float* __restrict__ bias, int has_res, int wsel,
    int fuse,
    const float* __restrict__ Wo, const float* __restrict__ bo,
    float* __restrict__ outv, int n) {
    __shared__ __align__(16) uint32_t Fs[128 * FS_ST];
    __shared__ __align__(16) uint32_t Ws[128 * WS_ST];
    __shared__ float sPart[128 * 2];

    const uint32_t* wh = g_Wh + wsel * 16384;

    const int tid  = threadIdx.x;
    const int wid  = tid >> 5;
    const int lane = tid & 31;
    const int gi   = lane >> 2;
    const int ti   = lane & 3;
    const int wr   = wid & 3;     // rows wr*32..+31
    const int wc   = wid >> 2;    // cols wc*64..+63
    const int base = blockIdx.x * 128;

    const int s_node = tid >> 1;
    const int s_half = tid & 1;   // 32-half segment within 64-half chunk
    const int gn_row = base + s_node;

    float acc[2][8][4];
#pragma unroll
    for (int mt = 0; mt < 2; mt++)
#pragma unroll
        for (int nt = 0; nt < 8; nt++)
#pragma unroll
            for (int q = 0; q < 4; q++) acc[mt][nt][q] = 0.f;

    uint4 pb[4], pa[4];
    // prefetch chunk 0 (A side from g_m, k0 = 0; 32-half segment per thread)
    {
        const uint4* bs = (const uint4*)wh;   // 1024 uint4 per chunk
#pragma unroll
        for (int r = 0; r < 4; r++) pb[r] = bs[r * 256 + tid];
        pa[0] = pa[1] = pa[2] = pa[3] = make_uint4(0, 0, 0, 0);
        if (gn_row < n) {
            const uint4* rp = (const uint4*)(g_m + (size_t)gn_row * HDIM + s_half * 32);
            pa[0] = rp[0]; pa[1] = rp[1]; pa[2] = rp[2]; pa[3] = rp[3];
        }
    }

    for (int kc = 0; kc < 4; kc++) {
        __syncthreads();   // smem free (prev chunk consumed)
        // store prefetched chunk: Ws [128 col][32 half2] stride 36
        {
#pragma unroll
            for (int r = 0; r < 4; r++) {
                int lin4 = r * 256 + tid;          // 0..1023
                int col = lin4 >> 3, c4 = lin4 & 7;
                *(uint4*)&Ws[col * WS_ST + c4 * 4] = pb[r];
            }
            uint32_t* fd = &Fs[s_node * FS_ST + s_half * 16];
            *(uint4*)(fd)      = pa[0];
            *(uint4*)(fd + 4)  = pa[1];
            *(uint4*)(fd + 8)  = pa[2];
            *(uint4*)(fd + 12) = pa[3];
        }
        __syncthreads();   // smem ready

        // prefetch next chunk (latency overlaps MMA below)
        if (kc < 3) {
            int kn = kc + 1;
            const uint4* bs = (const uint4*)(wh + kn * 4096);
#pragma unroll
            for (int r = 0; r < 4; r++) pb[r] = bs[r * 256 + tid];
            const __half* srcH = (kn < 2) ? g_m : g_fh;
            int k0 = (kn & 1) * 64;
            pa[0] = pa[1] = pa[2] = pa[3] = make_uint4(0, 0, 0, 0);
            if (gn_row < n) {
                const uint4* rp = (const uint4*)(srcH + (size_t)gn_row * HDIM + k0 + s_half * 32);
                pa[0] = rp[0]; pa[1] = rp[1]; pa[2] = rp[2]; pa[3] = rp[3];
            }
        }

#pragma unroll
        for (int ks = 0; ks < 4; ks++) {
            const int kb = ks * 8;
            uint32_t a[2][4];
#pragma unroll
            for (int mt = 0; mt < 2; mt++) {
                int rb = wr * 32 + mt * 16;
                a[mt][0] = Fs[(rb + gi)     * FS_ST + kb + ti];
                a[mt][1] = Fs[(rb + 8 + gi) * FS_ST + kb + ti];
                a[mt][2] = Fs[(rb + gi)     * FS_ST + kb + ti + 4];
                a[mt][3] = Fs[(rb + 8 + gi) * FS_ST + kb + ti + 4];
            }
#pragma unroll
            for (int nt = 0; nt < 8; nt++) {
                int cb = wc * 64 + nt * 8 + gi;
                uint32_t b0 = Ws[cb * WS_ST + kb + ti];
                uint32_t b1 = Ws[cb * WS_ST + kb + ti + 4];
                MMA_F16(acc[0][nt], a[0], b0, b1);
                MMA_F16(acc[1][nt], a[1], b0, b1);
            }
        }
    }

    // ---------------- epilogue ----------------
    float part[2][2] = {{0.f, 0.f}, {0.f, 0.f}};
#pragma unroll
    for (int nt = 0; nt < 8; nt++) {
        int col = wc * 64 + nt * 8 + ti * 2;
        float bb0 = bias[col], bb1 = bias[col + 1];
        float wo0 = 0.f, wo1 = 0.f;
        if (fuse) { wo0 = Wo[col]; wo1 = Wo[col + 1]; }
#pragma unroll
        for (int mt = 0; mt < 2; mt++) {
#pragma unroll
            for (int half = 0; half < 2; half++) {
                int row = base + wr * 32 + mt * 16 + gi + half * 8;
                if (row >= n) continue;
                float v0 = acc[mt][nt][half * 2 + 0] + bb0;
                float v1 = acc[mt][nt][half * 2 + 1] + bb1;
                v0 = (v0 > 0.f) ? v0 : expm1f(v0);
                v1 = (v1 > 0.f) ? v1 : expm1f(v1);
                size_t o = (size_t)row * HDIM + col;
                if (has_res) {
                    __half2 rh = *(const __half2*)(g_fh + o);
                    float2 rr = __half22float2(rh);
                    v0 += rr.x; v1 += rr.y;
                }
                if (fuse) {
                    part[mt][half] += v0 * wo0 + v1 * wo1;
                } else {
                    __half2 hv = __floats2half2_rn(v0, v1);
                    *(__half2*)(g_fh + o) = hv;
                }
            }
        }
    }

    if (fuse) {
#pragma unroll
        for (int mt = 0; mt < 2; mt++)
#pragma unroll
            for (int half = 0; half < 2; half++) {
                float p = part[mt][half];
                p += __shfl_xor_sync(0xffffffff, p, 1);
                p += __shfl_xor_sync(0xffffffff, p, 2);
                if (ti == 0) {
                    int rl = wr * 32 + mt * 16 + gi + half * 8;
                    sPart[rl * 2 + wc] = p;
                }
            }
        __syncthreads();
        if (tid < 128) {
            int row = base + tid;
            if (row < n) {
                float z = sPart[tid * 2] + sPart[tid * 2 + 1] + bo[0];
                outv[row] = 1.f / (1.f + expf(-z));
            }
        }
    }
}

// ---------------- launcher (kernel launches ONLY) ---------------------------
extern "C" void kernel_launch(void* const* d_in, const int* in_sizes, int n_in,
                              void* d_out, int out_size) {
    const float* x   = (const float*)d_in[0];
    const int*   ei  = (const int*)d_in[1];     // edge_index is int32
    const float* W1l = (const float*)d_in[2];
    const float* b1  = (const float*)d_in[3];
    const float* W1r = (const float*)d_in[4];
    const float* W2l = (const float*)d_in[5];
    const float* b2  = (const float*)d_in[6];
    const float* W2r = (const float*)d_in[7];
    const float* W3l = (const float*)d_in[8];
    const float* b3  = (const float*)d_in[9];
    const float* W3r = (const float*)d_in[10];
    const float* Wo  = (const float*)d_in[11];
    const float* bo  = (const float*)d_in[12];
    float* out = (float*)d_out;

    int N = in_sizes[0] / HDIM;
    int E = in_sizes[1] / 2;
    if (N > NMAX) N = NMAX;
    if (E > EMAX) E = EMAX;

    int total4 = N * HDIM / 4;

    // ---- fused setup: x->fp16, weight prep, flags, histogram ----
    k_setup<<<(total4 + 255) / 256, 256>>>(x, ei, W1l, W1r, W2l, W2r, W3l, W3r,
                                           N, total4, E);

    // ---- CSR build: scan (re-zeroes deg) + fill ----
    int nb = N / 1024 + 1;
    k_scan_all<<<nb, 1024>>>(N, E);
    k_fill    <<<(E + 255) / 256, 256>>>(ei, E, N);

    int aggBlocks   = (N * 16 + 255) / 256;
    int layerBlocks = (N + 127) / 128;

    // ---- layer 1: agg(x) -> GEMM -> fh = h1 ----
    k_agg      <<<aggBlocks, 256>>>(N);
    k_layer_mma<<<layerBlocks, 256>>>(b1, 0, 0, 0,
                                      (const float*)0, (const float*)0, (float*)0, N);

    // ---- layer 2: agg(h1) -> GEMM + residual -> fh = h2 ----
    k_agg      <<<aggBlocks, 256>>>(N);
    k_layer_mma<<<layerBlocks, 256>>>(b2, 1, 1, 0,
                                      (const float*)0, (const float*)0, (float*)0, N);

    // ---- layer 3: agg(h2) -> GEMM + residual + fused sigmoid head -> out ----
    k_agg      <<<aggBlocks, 256>>>(N);
    k_layer_mma<<<layerBlocks, 256>>>(b3, 1, 2, 1, Wo, bo, out, N);
}